// round 11
// baseline (speedup 1.0000x reference)
#include <cuda_runtime.h>
#include <cstdint>

// ParabolicPool2D: out[b,c,i,j] = max_{p,q in 0..2} f[b,c,2i+p,2j+q] + h[c,p,q]
// h[c,p,q] = -t[c]*(zp^2+zq^2)/2 -> separable with s = t[c]/2.
//
// Block = one (image, 32-output-row tile), 512 threads.
// Reads: 65 input rows as 4 back-to-back cp.async.bulk chunks (17/16/16/16)
//        with separate mbarriers; warp w computes row w then row w+16,
//        waiting only on the chunks those rows need (compute overlaps flight).
//        32-row tiles cut seam re-reads to 1.2%.
// Writes: results staged in smem (shifted by bo so smem==gmem mod 16), then
//        drained by ONE ~16KB cp.async.bulk shared->global sequential burst
//        plus <=3-float scalar head/tail.

#define Wd 256
#define OWd 127
#define OHd 127

#define IN_FLOATS  (65 * Wd)             // 16640 floats = 66560 B
#define OUT_FLOATS (32 * OWd + 4)        // 4068 floats (3-shift + pad)
#define MBAR_OFF   (IN_FLOATS + OUT_FLOATS)
#define SMEM_BYTES ((MBAR_OFF + 8) * 4 + 32)

__device__ __forceinline__ uint32_t smem_u32(const void* p) {
    return (uint32_t)__cvta_generic_to_shared(p);
}

__device__ __forceinline__ void mbar_wait(uint32_t mb, uint32_t parity) {
    asm volatile(
        "{\n\t.reg .pred P;\n\t"
        "W_%=:\n\t"
        "mbarrier.try_wait.parity.acquire.cta.shared::cta.b64 P, [%0], %1, 0x989680;\n\t"
        "@P bra.uni D_%=;\n\t"
        "bra.uni W_%=;\n\t"
        "D_%=:\n\t}"
        :: "r"(mb), "r"(parity) : "memory");
}

__device__ __forceinline__ void cm_row(const float* __restrict__ sr, int lane,
                                       float s, float cm[4]) {
    float4 a = *(const float4*)(sr + 4 * lane);
    float4 b = *(const float4*)(sr + 4 * lane + 128);
    float h0 = (lane == 0) ? b.x : a.x;
    int src = (lane + 1) & 31;
    float n0 = __shfl_sync(0xffffffffu, h0, src);   // col 4L+4
    float n1 = __shfl_sync(0xffffffffu, b.x, src);  // col 4L+132 (lane31 unused)
    cm[0] = fmaxf(fmaxf(a.x - s, a.y), a.z - s);    // out col 2L
    cm[1] = fmaxf(fmaxf(a.z - s, a.w), n0 - s);     // out col 2L+1
    cm[2] = fmaxf(fmaxf(b.x - s, b.y), b.z - s);    // out col 2L+64
    cm[3] = fmaxf(fmaxf(b.z - s, b.w), n1 - s);     // out col 2L+65
}

__device__ __forceinline__ void do_row(const float* __restrict__ buf, int i,
                                       float* __restrict__ smo, int bo,
                                       int lane, int j0, bool lastlane, float s) {
    const float* r0p = buf + (size_t)(2 * i) * Wd;
    float cmA[4], cmB[4], cmC[4];
    cm_row(r0p,          lane, s, cmA);
    cm_row(r0p + Wd,     lane, s, cmB);
    cm_row(r0p + 2 * Wd, lane, s, cmC);

    float o0 = fmaxf(fmaxf(cmA[0] - s, cmB[0]), cmC[0] - s);
    float o1 = fmaxf(fmaxf(cmA[1] - s, cmB[1]), cmC[1] - s);
    float o2 = fmaxf(fmaxf(cmA[2] - s, cmB[2]), cmC[2] - s);
    float o3 = fmaxf(fmaxf(cmA[3] - s, cmB[3]), cmC[3] - s);

    float* orow = smo + bo + i * OWd;
    orow[j0]      = o0;
    orow[j0 + 1]  = o1;
    orow[j0 + 64] = o2;
    if (!lastlane) orow[j0 + 65] = o3;
}

__global__ void __launch_bounds__(512, 2)
parabolic_pool2d_kernel(const float* __restrict__ f,
                        const float* __restrict__ t,
                        float* __restrict__ out) {
    extern __shared__ __align__(128) float sm[];
    float* smo = sm + IN_FLOATS;
    unsigned long long* mbar = (unsigned long long*)(sm + MBAR_OFF);

    int bid  = blockIdx.x;
    int img  = bid >> 2;                 // image = b*128 + c
    int tile = bid & 3;                  // 32-output-row tile within image
    int i0 = tile << 5;
    int nout = min(32, OHd - i0);        // 32, or 31 for tile 3
    int nin  = 2 * nout + 1;             // 65 or 63 input rows

    const float* src = f + (size_t)img * (256 * Wd) + (size_t)(i0 << 1) * Wd;

    const int coff[4] = {0, 17, 33, 49};
    int csz[4];
    csz[0] = 17; csz[1] = 16; csz[2] = 16; csz[3] = nin - 49;   // 16 or 14

    uint32_t sm_a = smem_u32(sm);
    uint32_t mb[4];
#pragma unroll
    for (int q = 0; q < 4; q++) mb[q] = smem_u32(&mbar[q]);

    if (threadIdx.x == 0) {
#pragma unroll
        for (int q = 0; q < 4; q++)
            asm volatile("mbarrier.init.shared.b64 [%0], 1;" :: "r"(mb[q]) : "memory");
    }
    __syncthreads();
    if (threadIdx.x == 0) {
#pragma unroll
        for (int q = 0; q < 4; q++) {
            int bytes = csz[q] * (Wd * 4);
            asm volatile("mbarrier.arrive.expect_tx.shared.b64 _, [%0], %1;"
                         :: "r"(mb[q]), "r"(bytes) : "memory");
            asm volatile("cp.async.bulk.shared::cta.global.mbarrier::complete_tx::bytes"
                         " [%0], [%1], %2, [%3];"
                         :: "r"(sm_a + coff[q] * Wd * 4), "l"(src + coff[q] * Wd),
                            "r"(bytes), "r"(mb[q]) : "memory");
        }
    }

    // output tile: contiguous nout*127 floats at gmem float index dst_f
    size_t dst_f = (size_t)img * (OHd * OWd) + (size_t)i0 * OWd;
    int bo = (int)(dst_f & 3);           // smem shift so smem==gmem (mod 16B)
    int total_f = nout * OWd;            // 4064 or 3937
    int head = (4 - bo) & 3;
    int middle = (total_f - head) & ~3;  // multiple of 4 floats (16B)
    int tailn = total_f - head - middle; // 0..3

    float s = 0.5f * __ldg(t + (img & 127));
    int tid  = threadIdx.x;
    int w    = tid >> 5;                 // 0..15
    int lane = tid & 31;
    int j0   = 2 * lane;
    bool lastlane = (lane == 31);

    // phase 1: output row w (inputs 2w..2w+2 <= 32)
    mbar_wait(mb[0], 0);
    if (w >= 8) mbar_wait(mb[1], 0);
    do_row(sm, w, smo, bo, lane, j0, lastlane, s);

    // phase 2: output row w+16 (inputs 32..64)
    if (w < 8) mbar_wait(mb[1], 0);
    mbar_wait(mb[2], 0);
    if (w >= 8) mbar_wait(mb[3], 0);
    int i = w + 16;
    if (i < nout)
        do_row(sm, i, smo, bo, lane, j0, lastlane, s);

    __syncthreads();                     // all results staged in smo

    float* gout = out + dst_f;
    if (tid < head)  gout[tid] = smo[bo + tid];
    if (tid < tailn) gout[head + middle + tid] = smo[bo + head + middle + tid];
    if (tid == 0) {
        asm volatile("fence.proxy.async.shared::cta;" ::: "memory");
        uint32_t ssrc = smem_u32(smo) + 4 * (bo + head);   // 16B aligned
        const float* gdst = gout + head;                    // 16B aligned
        asm volatile("cp.async.bulk.global.shared::cta.bulk_group [%0], [%1], %2;"
                     :: "l"(gdst), "r"(ssrc), "r"(middle * 4) : "memory");
        asm volatile("cp.async.bulk.commit_group;" ::: "memory");
        asm volatile("cp.async.bulk.wait_group 0;" ::: "memory");
    }
}

extern "C" void kernel_launch(void* const* d_in, const int* in_sizes, int n_in,
                              void* d_out, int out_size) {
    const float* f = (const float*)d_in[0];   // [16,128,256,256] fp32
    const float* t = (const float*)d_in[1];   // [128] fp32
    float* out = (float*)d_out;               // [16,128,127,127] fp32
    cudaFuncSetAttribute(parabolic_pool2d_kernel,
                         cudaFuncAttributeMaxDynamicSharedMemorySize, SMEM_BYTES);
    // 2048 images * 4 tiles = 8192 blocks, 512 threads each
    parabolic_pool2d_kernel<<<8192, 512, SMEM_BYTES>>>(f, t, out);
}

// round 12
// speedup vs baseline: 1.0337x; 1.0337x over previous
#include <cuda_runtime.h>
#include <cstdint>

// ParabolicPool2D: out[b,c,i,j] = max_{p,q in 0..2} f[b,c,2i+p,2j+q] + h[c,p,q]
// h[c,p,q] = -t[c]*(zp^2+zq^2)/2 -> separable with s = t[c]/2.
//
// Block = one (image, 16-output-row tile), 256 threads, 5 blocks/SM.
// Reads: 33 input rows as two cp.async.bulk chunks (17+16 rows); warp w
//        computes row w after chunk A, row w+8 after chunk B.
// Writes: rows staged in smem (shifted by bo so smem==gmem mod 16) and
//        drained as TWO sequential bulk bursts: burst 1 (rows 0-7) is issued
//        right after phase 1, overlapping phase-2 compute; burst 2 at the end.

#define Wd 256
#define OWd 127
#define OHd 127

#define OUTBUF 2040   // 3 (max shift) + 16*127 = 2035, padded

__device__ __forceinline__ uint32_t smem_u32(const void* p) {
    return (uint32_t)__cvta_generic_to_shared(p);
}

__device__ __forceinline__ void mbar_wait(uint32_t mb, uint32_t parity) {
    asm volatile(
        "{\n\t.reg .pred P;\n\t"
        "W_%=:\n\t"
        "mbarrier.try_wait.parity.acquire.cta.shared::cta.b64 P, [%0], %1, 0x989680;\n\t"
        "@P bra.uni D_%=;\n\t"
        "bra.uni W_%=;\n\t"
        "D_%=:\n\t}"
        :: "r"(mb), "r"(parity) : "memory");
}

__device__ __forceinline__ void cm_row(const float* __restrict__ sr, int lane,
                                       float s, float cm[4]) {
    float4 a = *(const float4*)(sr + 4 * lane);
    float4 b = *(const float4*)(sr + 4 * lane + 128);
    float h0 = (lane == 0) ? b.x : a.x;
    int src = (lane + 1) & 31;
    float n0 = __shfl_sync(0xffffffffu, h0, src);   // col 4L+4
    float n1 = __shfl_sync(0xffffffffu, b.x, src);  // col 4L+132 (lane31 unused)
    cm[0] = fmaxf(fmaxf(a.x - s, a.y), a.z - s);    // out col 2L
    cm[1] = fmaxf(fmaxf(a.z - s, a.w), n0 - s);     // out col 2L+1
    cm[2] = fmaxf(fmaxf(b.x - s, b.y), b.z - s);    // out col 2L+64
    cm[3] = fmaxf(fmaxf(b.z - s, b.w), n1 - s);     // out col 2L+65
}

__device__ __forceinline__ void do_row(const float* __restrict__ buf, int i,
                                       float* __restrict__ smo, int bo,
                                       int lane, int j0, bool lastlane, float s) {
    const float* r0p = buf + (size_t)(2 * i) * Wd;
    float cmA[4], cmB[4], cmC[4];
    cm_row(r0p,          lane, s, cmA);
    cm_row(r0p + Wd,     lane, s, cmB);
    cm_row(r0p + 2 * Wd, lane, s, cmC);

    float o0 = fmaxf(fmaxf(cmA[0] - s, cmB[0]), cmC[0] - s);
    float o1 = fmaxf(fmaxf(cmA[1] - s, cmB[1]), cmC[1] - s);
    float o2 = fmaxf(fmaxf(cmA[2] - s, cmB[2]), cmC[2] - s);
    float o3 = fmaxf(fmaxf(cmA[3] - s, cmB[3]), cmC[3] - s);

    float* orow = smo + bo + i * OWd;
    orow[j0]      = o0;
    orow[j0 + 1]  = o1;
    orow[j0 + 64] = o2;
    if (!lastlane) orow[j0 + 65] = o3;
}

// Drain gmem float range [lo,hi) of this tile from the staged smem buffer.
// Scalar head/tail (<=3 floats each) by low threads; aligned middle by one
// cp.async.bulk S->G (caller commits/waits the group).
__device__ __forceinline__ void drain(float* __restrict__ gbase,
                                      const float* __restrict__ smo,
                                      uint32_t smo_a, int bo, size_t dst_f,
                                      int lo, int hi, int tid) {
    int n = hi - lo;
    int a = (int)((dst_f + lo) & 3);
    int head = (4 - a) & 3;
    if (head > n) head = n;
    int middle = (n - head) & ~3;
    int tailn = n - head - middle;
    if (tid < head)  gbase[lo + tid] = smo[bo + lo + tid];
    if (tid < tailn) gbase[lo + head + middle + tid] = smo[bo + lo + head + middle + tid];
    if (tid == 0 && middle > 0) {
        asm volatile("fence.proxy.async.shared::cta;" ::: "memory");
        uint32_t ssrc = smo_a + 4 * (bo + lo + head);       // 16B aligned
        const float* gdst = gbase + lo + head;              // 16B aligned
        asm volatile("cp.async.bulk.global.shared::cta.bulk_group [%0], [%1], %2;"
                     :: "l"(gdst), "r"(ssrc), "r"(middle * 4) : "memory");
        asm volatile("cp.async.bulk.commit_group;" ::: "memory");
    }
}

__global__ void __launch_bounds__(256)
parabolic_pool2d_kernel(const float* __restrict__ f,
                        const float* __restrict__ t,
                        float* __restrict__ out) {
    __shared__ __align__(128) float smi[33 * Wd];   // 33 input rows (33792 B)
    __shared__ __align__(16)  float smo[OUTBUF];    // staged output (8160 B)
    __shared__ __align__(8) unsigned long long mbar[2];

    int bid  = blockIdx.x;
    int img  = bid >> 3;                 // image = b*128 + c
    int tile = bid & 7;                  // 16-output-row tile within image
    int i0 = tile << 4;
    int nout = min(16, OHd - i0);        // 16, or 15 for tile 7
    int nin  = 2 * nout + 1;             // 33 or 31 input rows
    int bytesA = 17 * (Wd * 4);
    int bytesB = (nin - 17) * (Wd * 4);

    const float* src = f + (size_t)img * (256 * Wd) + (size_t)(i0 << 1) * Wd;

    uint32_t smi_a = smem_u32(smi);
    uint32_t smo_a = smem_u32(smo);
    uint32_t mb0 = smem_u32(&mbar[0]);
    uint32_t mb1 = smem_u32(&mbar[1]);

    if (threadIdx.x == 0) {
        asm volatile("mbarrier.init.shared.b64 [%0], 1;" :: "r"(mb0) : "memory");
        asm volatile("mbarrier.init.shared.b64 [%0], 1;" :: "r"(mb1) : "memory");
    }
    __syncthreads();
    if (threadIdx.x == 0) {
        asm volatile("mbarrier.arrive.expect_tx.shared.b64 _, [%0], %1;"
                     :: "r"(mb0), "r"(bytesA) : "memory");
        asm volatile("cp.async.bulk.shared::cta.global.mbarrier::complete_tx::bytes"
                     " [%0], [%1], %2, [%3];"
                     :: "r"(smi_a), "l"(src), "r"(bytesA), "r"(mb0) : "memory");
        asm volatile("mbarrier.arrive.expect_tx.shared.b64 _, [%0], %1;"
                     :: "r"(mb1), "r"(bytesB) : "memory");
        asm volatile("cp.async.bulk.shared::cta.global.mbarrier::complete_tx::bytes"
                     " [%0], [%1], %2, [%3];"
                     :: "r"(smi_a + 17 * Wd * 4), "l"(src + 17 * Wd),
                        "r"(bytesB), "r"(mb1) : "memory");
    }

    size_t dst_f = (size_t)img * (OHd * OWd) + (size_t)i0 * OWd;
    int bo = (int)(dst_f & 3);           // smem shift so smem==gmem (mod 16B)
    int total_f = nout * OWd;            // 2032 or 1905
    int mid = 8 * OWd;                   // 1016: boundary between the 2 bursts

    float s = 0.5f * __ldg(t + (img & 127));
    int tid  = threadIdx.x;
    int w    = tid >> 5;
    int lane = tid & 31;
    int j0   = 2 * lane;
    bool lastlane = (lane == 31);
    float* gout = out + dst_f;

    // phase 1: output row w (inputs <= 16, chunk A)
    mbar_wait(mb0, 0);
    do_row(smi, w, smo, bo, lane, j0, lastlane, s);

    __syncthreads();                     // rows 0..7 staged
    drain(gout, smo, smo_a, bo, dst_f, 0, mid, tid);   // burst 1 overlaps phase 2

    // phase 2: output row w+8 (inputs 16..32, chunk B)
    mbar_wait(mb1, 0);
    int i = w + 8;
    if (i < nout)
        do_row(smi, i, smo, bo, lane, j0, lastlane, s);

    __syncthreads();                     // rows 8..nout-1 staged
    drain(gout, smo, smo_a, bo, dst_f, mid, total_f, tid);  // burst 2
    if (tid == 0)
        asm volatile("cp.async.bulk.wait_group 0;" ::: "memory");
}

extern "C" void kernel_launch(void* const* d_in, const int* in_sizes, int n_in,
                              void* d_out, int out_size) {
    const float* f = (const float*)d_in[0];   // [16,128,256,256] fp32
    const float* t = (const float*)d_in[1];   // [128] fp32
    float* out = (float*)d_out;               // [16,128,127,127] fp32
    // 2048 images * 8 tiles = 16384 blocks, 256 threads each
    parabolic_pool2d_kernel<<<16384, 256>>>(f, t, out);
}

// round 13
// speedup vs baseline: 1.0409x; 1.0070x over previous
#include <cuda_runtime.h>
#include <cstdint>

// ParabolicPool2D: out[b,c,i,j] = max_{p,q in 0..2} f[b,c,2i+p,2j+q] + h[c,p,q]
// h[c,p,q] = -t[c]*(zp^2+zq^2)/2 -> separable with s = t[c]/2:
//   colmax[r][j] = max(f[r][2j]-s, f[r][2j+1], f[r][2j+2]-s)
//   out[i][j]    = max(colmax[2i]-s, colmax[2i+1], colmax[2i+2]-s)
//
// Fine-grained block = one (image, 8-output-row tile), 128 threads,
// ~21.6KB smem -> 10 blocks/SM (40 warps, 2x more concurrent bulk streams
// than the 16-row version). Reads: one 17-row cp.async.bulk (17.4KB
// sequential burst). Writes: tile staged in smem (shifted so smem==gmem
// mod 16) and drained as one ~4KB cp.async.bulk shared->global burst.

#define Wd 256
#define OWd 127
#define OHd 127

#define NIN_MAX 17
#define OUTBUF 1024   // 3 (max shift) + 8*127 = 1019, padded

__device__ __forceinline__ uint32_t smem_u32(const void* p) {
    return (uint32_t)__cvta_generic_to_shared(p);
}

__device__ __forceinline__ void mbar_wait(uint32_t mb, uint32_t parity) {
    asm volatile(
        "{\n\t.reg .pred P;\n\t"
        "W_%=:\n\t"
        "mbarrier.try_wait.parity.acquire.cta.shared::cta.b64 P, [%0], %1, 0x989680;\n\t"
        "@P bra.uni D_%=;\n\t"
        "bra.uni W_%=;\n\t"
        "D_%=:\n\t}"
        :: "r"(mb), "r"(parity) : "memory");
}

__device__ __forceinline__ void cm_row(const float* __restrict__ sr, int lane,
                                       float s, float cm[4]) {
    float4 a = *(const float4*)(sr + 4 * lane);
    float4 b = *(const float4*)(sr + 4 * lane + 128);
    float h0 = (lane == 0) ? b.x : a.x;
    int src = (lane + 1) & 31;
    float n0 = __shfl_sync(0xffffffffu, h0, src);   // col 4L+4
    float n1 = __shfl_sync(0xffffffffu, b.x, src);  // col 4L+132 (lane31 unused)
    cm[0] = fmaxf(fmaxf(a.x - s, a.y), a.z - s);    // out col 2L
    cm[1] = fmaxf(fmaxf(a.z - s, a.w), n0 - s);     // out col 2L+1
    cm[2] = fmaxf(fmaxf(b.x - s, b.y), b.z - s);    // out col 2L+64
    cm[3] = fmaxf(fmaxf(b.z - s, b.w), n1 - s);     // out col 2L+65
}

__device__ __forceinline__ void do_row(const float* __restrict__ buf, int i,
                                       float* __restrict__ smo, int bo,
                                       int lane, int j0, bool lastlane, float s) {
    const float* r0p = buf + (size_t)(2 * i) * Wd;
    float cmA[4], cmB[4], cmC[4];
    cm_row(r0p,          lane, s, cmA);
    cm_row(r0p + Wd,     lane, s, cmB);
    cm_row(r0p + 2 * Wd, lane, s, cmC);

    float o0 = fmaxf(fmaxf(cmA[0] - s, cmB[0]), cmC[0] - s);
    float o1 = fmaxf(fmaxf(cmA[1] - s, cmB[1]), cmC[1] - s);
    float o2 = fmaxf(fmaxf(cmA[2] - s, cmB[2]), cmC[2] - s);
    float o3 = fmaxf(fmaxf(cmA[3] - s, cmB[3]), cmC[3] - s);

    float* orow = smo + bo + i * OWd;
    orow[j0]      = o0;
    orow[j0 + 1]  = o1;
    orow[j0 + 64] = o2;
    if (!lastlane) orow[j0 + 65] = o3;
}

__global__ void __launch_bounds__(128, 10)
parabolic_pool2d_kernel(const float* __restrict__ f,
                        const float* __restrict__ t,
                        float* __restrict__ out) {
    __shared__ __align__(128) float smi[NIN_MAX * Wd];  // 17 input rows (17408 B)
    __shared__ __align__(16)  float smo[OUTBUF];        // staged output (4096 B)
    __shared__ __align__(8) unsigned long long mbar;

    int bid  = blockIdx.x;
    int img  = bid >> 4;                 // image = b*128 + c
    int tile = bid & 15;                 // 8-output-row tile within image
    int i0 = tile << 3;
    int nout = min(8, OHd - i0);         // 8, or 7 for tile 15
    int nin  = 2 * nout + 1;             // 17 or 15 input rows
    int bytes = nin * (Wd * 4);          // 17408 or 15360

    const float* src = f + (size_t)img * (256 * Wd) + (size_t)(i0 << 1) * Wd;

    uint32_t smi_a = smem_u32(smi);
    uint32_t smo_a = smem_u32(smo);
    uint32_t mb_a  = smem_u32(&mbar);

    if (threadIdx.x == 0) {
        asm volatile("mbarrier.init.shared.b64 [%0], 1;" :: "r"(mb_a) : "memory");
    }
    __syncthreads();
    if (threadIdx.x == 0) {
        asm volatile("mbarrier.arrive.expect_tx.shared.b64 _, [%0], %1;"
                     :: "r"(mb_a), "r"(bytes) : "memory");
        asm volatile("cp.async.bulk.shared::cta.global.mbarrier::complete_tx::bytes"
                     " [%0], [%1], %2, [%3];"
                     :: "r"(smi_a), "l"(src), "r"(bytes), "r"(mb_a) : "memory");
    }

    size_t dst_f = (size_t)img * (OHd * OWd) + (size_t)i0 * OWd;
    int bo = (int)(dst_f & 3);           // smem shift so smem==gmem (mod 16B)
    int total_f = nout * OWd;            // 1016 or 889
    int head = (4 - bo) & 3;
    int middle = (total_f - head) & ~3;  // multiple of 4 floats (16B)
    int tailn = total_f - head - middle; // 0..3

    float s = 0.5f * __ldg(t + (img & 127));
    int tid  = threadIdx.x;
    int w    = tid >> 5;                 // 0..3
    int lane = tid & 31;
    int j0   = 2 * lane;
    bool lastlane = (lane == 31);

    mbar_wait(mb_a, 0);

    // warp w computes output rows w and w+4
    do_row(smi, w, smo, bo, lane, j0, lastlane, s);
    int i = w + 4;
    if (i < nout)
        do_row(smi, i, smo, bo, lane, j0, lastlane, s);

    __syncthreads();                     // all results staged in smo

    float* gout = out + dst_f;
    if (tid < head)  gout[tid] = smo[bo + tid];
    if (tid < tailn) gout[head + middle + tid] = smo[bo + head + middle + tid];
    if (tid == 0) {
        asm volatile("fence.proxy.async.shared::cta;" ::: "memory");
        uint32_t ssrc = smo_a + 4 * (bo + head);            // 16B aligned
        const float* gdst = gout + head;                    // 16B aligned
        asm volatile("cp.async.bulk.global.shared::cta.bulk_group [%0], [%1], %2;"
                     :: "l"(gdst), "r"(ssrc), "r"(middle * 4) : "memory");
        asm volatile("cp.async.bulk.commit_group;" ::: "memory");
        asm volatile("cp.async.bulk.wait_group 0;" ::: "memory");
    }
}

extern "C" void kernel_launch(void* const* d_in, const int* in_sizes, int n_in,
                              void* d_out, int out_size) {
    const float* f = (const float*)d_in[0];   // [16,128,256,256] fp32
    const float* t = (const float*)d_in[1];   // [128] fp32
    float* out = (float*)d_out;               // [16,128,127,127] fp32
    // 2048 images * 16 tiles = 32768 blocks, 128 threads each
    parabolic_pool2d_kernel<<<32768, 128>>>(f, t, out);
}